// round 11
// baseline (speedup 1.0000x reference)
#include <cuda_runtime.h>
#include <cuda_bf16.h>

#define BB 4
#define SS 1024
#define DD 2048
#define KSPLIT 4
#define KCHUNK (DD / KSPLIT)   // 512 floats per K-chunk
#define ROWTILE 32
#define NRG (DD / ROWTILE)     // 64 row groups -> 256 gemv work items
#define NBLOCKS 296            // 2 blocks/SM on 148 SMs; <= capacity on 152 too
#define NTHREADS 256

// Scratch + barrier state (allocation-free rule: __device__ globals, device-side refs only)
__device__ float g_vp[KSPLIT][BB][DD];
__device__ float g_op[KSPLIT][BB][DD];
__device__ unsigned g_bar_count;           // self-resets at each barrier
__device__ volatile unsigned g_bar_sense;  // cycles 1,2 per launch; replay-safe

__device__ __forceinline__ float4 f4add(float4 a, float4 b) {
    return make_float4(a.x + b.x, a.y + b.y, a.z + b.z, a.w + b.w);
}

// Sense-reversing grid barrier. All NBLOCKS are co-resident by construction
// (launch_bounds caps regs at 128, smem 9KB -> 2 blocks/SM guaranteed).
__device__ __forceinline__ void grid_barrier(unsigned phase) {
    __threadfence();          // publish this thread's prior global writes
    __syncthreads();
    if (threadIdx.x == 0) {
        unsigned arrived = atomicAdd(&g_bar_count, 1);
        if (arrived == NBLOCKS - 1) {
            atomicExch(&g_bar_count, 0);
            __threadfence();
            g_bar_sense = phase;
        } else {
            while (g_bar_sense != phase) __nanosleep(32);
            __threadfence();
        }
    }
    __syncthreads();
}

// Partial GEMV phase (R7 structure): 8-row register blocking, K-split x4.
// Work item bid in [0,256): kc = bid&3, rg = bid>>2. 32 rows x 512-float chunk.
// STAGE 0: x = cond, writes g_vp. STAGE 1: x = sum g_vp + bv, writes g_op.
template<int STAGE>
__device__ __forceinline__ void gemv_phase(const float* __restrict__ W,
                                           const float* __restrict__ xg,
                                           float* xs_raw, float* pr_raw,
                                           int bid, int tid) {
    float (*xs)[KCHUNK] = (float (*)[KCHUNK])xs_raw;
    float (*pr)[ROWTILE] = (float (*)[ROWTILE])pr_raw;
    float* __restrict__ yp = (STAGE == 0) ? &g_vp[0][0][0] : &g_op[0][0][0];

    const int kc = bid & (KSPLIT - 1);
    const int rg = bid >> 2;

    for (int i = tid; i < BB * KCHUNK; i += NTHREADS) {
        const int b = i >> 9;
        const int k = i & (KCHUNK - 1);
        if (STAGE == 0) {
            xs[b][k] = xg[b * DD + kc * KCHUNK + k];
        } else {
            const int gk = kc * KCHUNK + k;
            xs[b][k] = g_vp[0][b][gk] + g_vp[1][b][gk] +
                       g_vp[2][b][gk] + g_vp[3][b][gk] + xg[gk];
        }
    }
    __syncthreads();

    const int wid  = tid >> 5;
    const int lane = tid & 31;
    const int rw   = wid >> 1;
    const int kw   = wid & 1;
    const int r0   = rg * ROWTILE + rw * 8;

    float acc[32];
    #pragma unroll
    for (int i = 0; i < 32; ++i) acc[i] = 0.f;

    const float4* xs0 = (const float4*)xs[0];
    const float4* xs1 = (const float4*)xs[1];
    const float4* xs2 = (const float4*)xs[2];
    const float4* xs3 = (const float4*)xs[3];

    #pragma unroll
    for (int step = 0; step < 2; ++step) {
        const int k4 = kw * 64 + step * 32 + lane;
        const float4* Wb = (const float4*)W + (size_t)(kc * (KCHUNK / 4)) + k4;

        float4 w[8];
        #pragma unroll
        for (int r = 0; r < 8; ++r)
            w[r] = Wb[(size_t)(r0 + r) * (DD / 4)];

        const float4 x0 = xs0[k4];
        const float4 x1 = xs1[k4];
        const float4 x2 = xs2[k4];
        const float4 x3 = xs3[k4];

        #pragma unroll
        for (int r = 0; r < 8; ++r) {
            acc[r * 4 + 0] += w[r].x * x0.x + w[r].y * x0.y + w[r].z * x0.z + w[r].w * x0.w;
            acc[r * 4 + 1] += w[r].x * x1.x + w[r].y * x1.y + w[r].z * x1.z + w[r].w * x1.w;
            acc[r * 4 + 2] += w[r].x * x2.x + w[r].y * x2.y + w[r].z * x2.z + w[r].w * x2.w;
            acc[r * 4 + 3] += w[r].x * x3.x + w[r].y * x3.y + w[r].z * x3.z + w[r].w * x3.w;
        }
    }

    // Butterfly: 32 values/lane -> lane l holds output (row r0+(l>>2), batch l&3).
    int L = 32;
    #pragma unroll
    for (int m = 16; m >= 1; m >>= 1) {
        L >>= 1;
        const bool up = (lane & m) != 0;
        #pragma unroll
        for (int j = 0; j < L; ++j) {
            const float send = up ? acc[j] : acc[j + L];
            const float recv = __shfl_xor_sync(0xffffffffu, send, m);
            acc[j] = (up ? acc[j + L] : acc[j]) + recv;
        }
    }

    pr[wid][lane] = acc[0];
    __syncthreads();

    if (tid < 128) {
        const int rw2 = tid >> 5;
        const int l   = tid & 31;
        const float s = pr[rw2 * 2][l] + pr[rw2 * 2 + 1][l];
        const int row = rg * ROWTILE + rw2 * 8 + (l >> 2);
        const int b   = l & 3;
        yp[((size_t)kc * BB + b) * DD + row] = s;
    }
    __syncthreads();
}

__global__ __launch_bounds__(NTHREADS, 2) void fused_kernel(
    const float* __restrict__ cond,
    const float* __restrict__ Wv,
    const float* __restrict__ bv,
    const float* __restrict__ Wo,
    const float* __restrict__ bo,
    float4* __restrict__ out)
{
    __shared__ float xs[BB][KCHUNK];   // 8 KB
    __shared__ float pr[8][ROWTILE];   // 1 KB

    const int bid = blockIdx.x;
    const int tid = threadIdx.x;

    // Phase A: g_vp = partial(Wv @ cond)
    if (bid < NRG * KSPLIT)
        gemv_phase<0>(Wv, cond, &xs[0][0], &pr[0][0], bid, tid);
    grid_barrier(1);

    // Phase B: g_op = partial(Wo @ (sum g_vp + bv))
    if (bid < NRG * KSPLIT)
        gemv_phase<1>(Wo, bv, &xs[0][0], &pr[0][0], bid, tid);
    grid_barrier(2);

    // Phase C: out[b][s][:] = sum_kc g_op + bo, broadcast over s.
    const float4* op  = (const float4*)g_op;
    const float4* bo4 = (const float4*)bo;
    const int nitems = BB * SS * (DD / 4) / 8;   // 262144 owner items, 8 stores each
    for (int t = bid * NTHREADS + tid; t < nitems; t += NBLOCKS * NTHREADS) {
        const int d4 = t & 511;
        const int g  = t >> 9;
        const int b  = g >> 7;
        const int s8 = (g & 127) * 8;
        float4 o = f4add(f4add(op[(0 * BB + b) * 512 + d4], op[(1 * BB + b) * 512 + d4]),
                         f4add(op[(2 * BB + b) * 512 + d4], op[(3 * BB + b) * 512 + d4]));
        o = f4add(o, bo4[d4]);
        float4* dst = out + ((size_t)(b * SS + s8) * 512) + d4;
        #pragma unroll
        for (int i = 0; i < 8; ++i)
            dst[(size_t)i * 512] = o;
    }
}

extern "C" void kernel_launch(void* const* d_in, const int* in_sizes, int n_in,
                              void* d_out, int out_size) {
    // Inputs: hidden_states, condition, Wq, bq, Wk, bk, Wv, bv, Wo, bo
    const float* cond = (const float*)d_in[1];
    const float* Wv   = (const float*)d_in[6];
    const float* bv   = (const float*)d_in[7];
    const float* Wo   = (const float*)d_in[8];
    const float* bo   = (const float*)d_in[9];
    float* out = (float*)d_out;

    fused_kernel<<<NBLOCKS, NTHREADS>>>(cond, Wv, bv, Wo, bo, (float4*)out);
}